// round 16
// baseline (speedup 1.0000x reference)
#include <cuda_runtime.h>
#include <cuda_bf16.h>
#include <cstdint>

typedef __nv_bfloat16 bf16;

// ---------------- problem constants ----------------
#define NN   16384
#define FF   128
#define RR   16
#define HH   8
#define CC   64
#define HC   512
#define NE   163840
#define NEP  180224          // NE + NN self loops
#define NEG_SLOPE 0.2f
#define SELF_FILL 0.5f

// ---------------- device scratch (only ever touched from device code) ----------------
__device__ int   g_src32[NE];
__device__ int   g_dst32[NE];
__device__ int   g_deg[NN];          // zero at module load; k_scan resets to zero each run
__device__ int   g_off[NN + 1];
__device__ int   g_fill[NN];
__device__ int   g_csr_src[NEP];
__device__ int   g_csr_eid[NEP];
__device__ float g_xl1[(size_t)NN * HC];
__device__ float g_xr1[(size_t)NN * HC];
__device__ float g_xl2[(size_t)NN * HC];
__device__ float g_xr2[(size_t)NN * HC];
__device__ __align__(16) bf16 g_xs_hi[(size_t)NN * FF];
__device__ __align__(16) bf16 g_xs_lo[(size_t)NN * FF];
__device__ __align__(16) bf16 g_hs_hi[(size_t)NN * HC];
__device__ __align__(16) bf16 g_hs_lo[(size_t)NN * HC];
__device__ __align__(16) bf16 g_wl_hi[HC * FF];
__device__ __align__(16) bf16 g_wl_lo[HC * FF];
__device__ __align__(16) bf16 g_wr_hi[HC * FF];
__device__ __align__(16) bf16 g_wr_lo[HC * FF];
__device__ __align__(16) bf16 g_w2l_hi[HC * HC];
__device__ __align__(16) bf16 g_w2l_lo[HC * HC];
__device__ __align__(16) bf16 g_w2r_hi[HC * HC];
__device__ __align__(16) bf16 g_w2r_lo[HC * HC];

// ---------------- asm helpers ----------------
#define LDSM_X4(r0, r1, r2, r3, a) \
    asm volatile("ldmatrix.sync.aligned.m8n8.x4.shared.b16 {%0,%1,%2,%3}, [%4];" \
                 : "=r"(r0), "=r"(r1), "=r"(r2), "=r"(r3) : "r"(a))

#define MMA_BF16(d, a0, a1, a2, a3, b0, b1) \
    asm volatile("mma.sync.aligned.m16n8k16.row.col.f32.bf16.bf16.f32 " \
                 "{%0,%1,%2,%3}, {%4,%5,%6,%7}, {%8,%9}, {%0,%1,%2,%3};" \
                 : "+f"((d)[0]), "+f"((d)[1]), "+f"((d)[2]), "+f"((d)[3]) \
                 : "r"(a0), "r"(a1), "r"(a2), "r"(a3), "r"(b0), "r"(b1))

#define CP_ASYNC16(dst, src) \
    asm volatile("cp.async.cg.shared.global [%0], [%1], 16;" :: "r"(dst), "l"(src))
#define CP_COMMIT()  asm volatile("cp.async.commit_group;" ::: "memory")
#define CP_WAIT0()   asm volatile("cp.async.wait_group 0;" ::: "memory")
#define CP_WAIT1()   asm volatile("cp.async.wait_group 1;" ::: "memory")

__device__ __forceinline__ uint32_t smem_to_u32(const void* p) {
    uint32_t a;
    asm("{ .reg .u64 t; cvta.to.shared.u64 t, %1; cvt.u32.u64 %0, t; }" : "=r"(a) : "l"(p));
    return a;
}
__device__ __forceinline__ void fma2(unsigned long long& d, unsigned long long a,
                                     unsigned long long b) {
    asm("fma.rn.f32x2 %0, %1, %2, %0;" : "+l"(d) : "l"(a), "l"(b));
}
__device__ __forceinline__ unsigned long long pack2(float a, float b) {
    unsigned long long r;
    asm("mov.b64 %0, {%1, %2};" : "=l"(r) : "f"(a), "f"(b));
    return r;
}
__device__ __forceinline__ float2 unpack2(unsigned long long v) {
    float2 f;
    asm("mov.b64 {%0, %1}, %2;" : "=f"(f.x), "=f"(f.y) : "l"(v));
    return f;
}
__device__ __forceinline__ uint32_t pkbf(bf16 a, bf16 b) {
    uint16_t ua = *(uint16_t*)&a, ub = *(uint16_t*)&b;
    return (uint32_t)ua | ((uint32_t)ub << 16);
}
__device__ __forceinline__ void split1(float v, bf16& h, bf16& l) {
    h = __float2bfloat16(v);
    l = __float2bfloat16(v - __bfloat162float(h));
}

// ---------------- bf16 HMMA GEMM body (proven: 128x128, 256 thr, 2-stage) ----------------
#define KC       16
#define SPITCH   48
#define TILE_SB  (128 * SPITCH)     // 6144
#define STAGE_B  (4 * TILE_SB)      // 24576; 2 stages = 49152 static smem

__device__ __forceinline__ void cp_tile(uint32_t smDst, const bf16* __restrict__ g,
                                        size_t row0, int K, int kt, int tid) {
    const char* gb = (const char*)(g + row0 * (size_t)K + (size_t)kt * KC);
    size_t pitchG = (size_t)K * 2;
    int row = tid >> 1, c = (tid & 1) * 16;
    CP_ASYNC16(smDst + (uint32_t)(row * SPITCH + c), gb + (size_t)row * pitchG + c);
}

__device__ __forceinline__ void mma_body(const bf16* __restrict__ Ah,
                                         const bf16* __restrict__ Al, int K,
                                         const bf16* __restrict__ Bh,
                                         const bf16* __restrict__ Bl,
                                         const float* __restrict__ bias,
                                         float* __restrict__ C) {
    __shared__ __align__(16) char smem[2 * STAGE_B];
    uint32_t sb = smem_to_u32(smem);
    int tid = threadIdx.x;
    int wid = tid >> 5, lane = tid & 31;
    int wm = wid & 1, wn = wid >> 1;
    size_t rowBase = (size_t)blockIdx.y * 128;
    size_t colBase = (size_t)blockIdx.x * 128;
    int nc = K / KC;

    float acc[4][4][4];
#pragma unroll
    for (int a = 0; a < 4; a++)
#pragma unroll
        for (int b = 0; b < 4; b++)
#pragma unroll
            for (int q = 0; q < 4; q++) acc[a][b][q] = 0.f;

    uint32_t kbyte = (uint32_t)((lane >> 4) * 16);
    uint32_t aOff = (uint32_t)((wm * 64 + (lane & 15)) * SPITCH) + kbyte;
    uint32_t bOff = (uint32_t)((wn * 32 + (lane & 15)) * SPITCH) + kbyte;

    {
        uint32_t st = sb;
        cp_tile(st + 0 * TILE_SB, Ah, rowBase, K, 0, tid);
        cp_tile(st + 1 * TILE_SB, Al, rowBase, K, 0, tid);
        cp_tile(st + 2 * TILE_SB, Bh, colBase, K, 0, tid);
        cp_tile(st + 3 * TILE_SB, Bl, colBase, K, 0, tid);
        CP_COMMIT();
    }

    for (int c = 0; c < nc; c++) {
        if (c + 1 < nc) {
            uint32_t st = sb + ((c + 1) & 1) * STAGE_B;
            cp_tile(st + 0 * TILE_SB, Ah, rowBase, K, c + 1, tid);
            cp_tile(st + 1 * TILE_SB, Al, rowBase, K, c + 1, tid);
            cp_tile(st + 2 * TILE_SB, Bh, colBase, K, c + 1, tid);
            cp_tile(st + 3 * TILE_SB, Bl, colBase, K, c + 1, tid);
            CP_COMMIT();
            CP_WAIT1();
        } else {
            CP_WAIT0();
        }
        __syncthreads();

        uint32_t st = sb + (c & 1) * STAGE_B;
        uint32_t ahB = st + 0 * TILE_SB + aOff;
        uint32_t alB = st + 1 * TILE_SB + aOff;
        uint32_t bhB = st + 2 * TILE_SB + bOff;
        uint32_t blB = st + 3 * TILE_SB + bOff;

        uint32_t ah[4][4], al[4][4], bh[2][4], bl[2][4];
#pragma unroll
        for (int mt = 0; mt < 4; mt++) {
            LDSM_X4(ah[mt][0], ah[mt][1], ah[mt][2], ah[mt][3], ahB + mt * 16 * SPITCH);
            LDSM_X4(al[mt][0], al[mt][1], al[mt][2], al[mt][3], alB + mt * 16 * SPITCH);
        }
#pragma unroll
        for (int p = 0; p < 2; p++) {
            LDSM_X4(bh[p][0], bh[p][1], bh[p][2], bh[p][3], bhB + p * 16 * SPITCH);
            LDSM_X4(bl[p][0], bl[p][1], bl[p][2], bl[p][3], blB + p * 16 * SPITCH);
        }
#pragma unroll
        for (int mt = 0; mt < 4; mt++)
#pragma unroll
            for (int nt = 0; nt < 4; nt++) {
                int p = nt >> 1, q = nt & 1;
                MMA_BF16(acc[mt][nt], ah[mt][0], ah[mt][1], ah[mt][2], ah[mt][3],
                         bh[p][q], bh[p][q + 2]);
                MMA_BF16(acc[mt][nt], ah[mt][0], ah[mt][1], ah[mt][2], ah[mt][3],
                         bl[p][q], bl[p][q + 2]);
                MMA_BF16(acc[mt][nt], al[mt][0], al[mt][1], al[mt][2], al[mt][3],
                         bh[p][q], bh[p][q + 2]);
            }
        __syncthreads();
    }

#pragma unroll
    for (int mt = 0; mt < 4; mt++) {
        size_t row = rowBase + wm * 64 + mt * 16 + (lane >> 2);
#pragma unroll
        for (int nt = 0; nt < 4; nt++) {
            size_t col = colBase + wn * 32 + nt * 8 + (lane & 3) * 2;
            float b0 = bias[col], b1 = bias[col + 1];
            *(float2*)(C + row * HC + col) =
                make_float2(acc[mt][nt][0] + b0, acc[mt][nt][1] + b1);
            *(float2*)(C + (row + 8) * HC + col) =
                make_float2(acc[mt][nt][2] + b0, acc[mt][nt][3] + b1);
        }
    }
}

// ---------------- prep1: x split + layer-1 weight transposes (one launch) ----------------
// blocks [0, 8192): x split; [8192, 8448): Wl1; [8448, 8704): Wr1
__global__ void k_prep1(const float* __restrict__ x, const float* __restrict__ Wl1,
                        const float* __restrict__ Wr1) {
    int b = blockIdx.x, tid = threadIdx.x;
    if (b < 8192) {
        int i = b * 256 + tid;               // < NN*FF = 2097152
        split1(x[i], g_xs_hi[i], g_xs_lo[i]);
    } else if (b < 8448) {
        int i = (b - 8192) * 256 + tid;      // < HC*FF = 65536
        int n = i / FF, k = i % FF;
        split1(Wl1[(size_t)k * HC + n], g_wl_hi[i], g_wl_lo[i]);
    } else {
        int i = (b - 8448) * 256 + tid;
        int n = i / FF, k = i % FF;
        split1(Wr1[(size_t)k * HC + n], g_wr_hi[i], g_wr_lo[i]);
    }
}

// ---------------- mega1: layer-1 GEMM pair + tail helpers ----------------
// z=0: xl1 GEMM; z=1: xr1 GEMM; z=2 (512 CTAs): convert (with local dtype detect)
// and layer-2 weight transposes into separate g_w2* buffers (no race with z<2 reads).
__global__ __launch_bounds__(256, 2) void k_mega1(const float* bl, const float* br,
                                                  const void* ei,
                                                  const float* __restrict__ Wl2,
                                                  const float* __restrict__ Wr2) {
    if (blockIdx.z == 0) {
        mma_body(g_xs_hi, g_xs_lo, FF, g_wl_hi, g_wl_lo, bl, g_xl1);
        return;
    }
    if (blockIdx.z == 1) {
        mma_body(g_xs_hi, g_xs_lo, FF, g_wr_hi, g_wr_lo, br, g_xr1);
        return;
    }
    int hb = blockIdx.y * gridDim.x + blockIdx.x;   // 0..511
    int tid = threadIdx.x;
    if (hb < 256) {
        // per-block dtype detect (deterministic, redundant across blocks)
        __shared__ int ok;
        if (tid == 0) ok = 1;
        __syncthreads();
        const long long* p64 = (const long long*)ei;
        int bad = 0;
        for (int i = tid; i < 2048; i += 256) {
            long long v = p64[i];
            if (v < 0 || v >= NN) bad = 1;
        }
        if (bad) ok = 0;
        __syncthreads();
        int is64 = ok;
        for (int e = hb * 256 + tid; e < NE; e += 256 * 256) {
            int s, d;
            if (is64) { s = (int)p64[e]; d = (int)p64[NE + e]; }
            else { const int* p = (const int*)ei; s = p[e]; d = p[NE + e]; }
            g_src32[e] = s; g_dst32[e] = d;
            atomicAdd(&g_deg[d], 1);
        }
    } else {
        // layer-2 weight transpose+split into dedicated buffers
        int base = (hb - 256) * 256 + tid;
        for (int i = base; i < HC * HC; i += 256 * 256) {
            int n = i / HC, k = i % HC;
            split1(Wl2[(size_t)k * HC + n], g_w2l_hi[i], g_w2l_lo[i]);
            split1(Wr2[(size_t)k * HC + n], g_w2r_hi[i], g_w2r_lo[i]);
        }
    }
}

// ---------------- scan: offsets with implicit +1 self loop; resets g_deg ----------------
__global__ void k_scan() {
    const int PER = NN / 1024;
    int t = threadIdx.x, lane = t & 31, warp = t >> 5;
    int base = t * PER;
    int loc[PER]; int run = 0;
#pragma unroll
    for (int i = 0; i < PER; i++) {
        loc[i] = run;
        run += g_deg[base + i] + 1;      // +1 = self loop
        g_deg[base + i] = 0;             // reset for next graph replay
    }
    int v = run;
#pragma unroll
    for (int o = 1; o < 32; o <<= 1) { int u = __shfl_up_sync(~0u, v, o); if (lane >= o) v += u; }
    __shared__ int ws[32];
    if (lane == 31) ws[warp] = v;
    __syncthreads();
    if (warp == 0) {
        int w = ws[lane];
#pragma unroll
        for (int o = 1; o < 32; o <<= 1) { int u = __shfl_up_sync(~0u, w, o); if (lane >= o) w += u; }
        ws[lane] = w;
    }
    __syncthreads();
    int excl = (warp ? ws[warp - 1] : 0) + (v - run);
#pragma unroll
    for (int i = 0; i < PER; i++) { int o = excl + loc[i]; g_off[base + i] = o; g_fill[base + i] = o; }
    if (t == 1023) g_off[NN] = excl + run;
}
__global__ void k_scatter() {
    int e = blockIdx.x * blockDim.x + threadIdx.x;
    if (e >= NEP) return;
    int s = (e < NE) ? g_src32[e] : (e - NE);
    int d = (e < NE) ? g_dst32[e] : (e - NE);
    int pos = atomicAdd(&g_fill[d], 1);
    g_csr_src[pos] = s; g_csr_eid[pos] = e;
}
__global__ void k_sort() {
    int n = blockIdx.x * blockDim.x + threadIdx.x;
    if (n >= NN) return;
    int b = g_off[n], e = g_off[n + 1];
    for (int i = b + 1; i < e; i++) {
        int ke = g_csr_eid[i], ks = g_csr_src[i];
        int j = i - 1;
        while (j >= b && g_csr_eid[j] > ke) {
            g_csr_eid[j + 1] = g_csr_eid[j]; g_csr_src[j + 1] = g_csr_src[j]; j--;
        }
        g_csr_eid[j + 1] = ke; g_csr_src[j + 1] = ks;
    }
}

// ---------------- layer-2 GEMM pair (z selects path; reads g_w2* buffers) ----------------
__global__ __launch_bounds__(256, 2) void k_mma_x2(const float* bl, const float* br) {
    if (blockIdx.z == 0)
        mma_body(g_hs_hi, g_hs_lo, HC, g_w2l_hi, g_w2l_lo, bl, g_xl2);
    else
        mma_body(g_hs_hi, g_hs_lo, HC, g_w2r_hi, g_w2r_lo, br, g_xr2);
}

// ---------------- GATv2 edge pass with FUSED edge-feature transform ----------------
__device__ __forceinline__ void gat_edge_fused(const float* __restrict__ xl,
                                               const float* __restrict__ xr,
                                               const float* __restrict__ ea,
                                               const float* __restrict__ We,
                                               const float* __restrict__ att,
                                               const float* __restrict__ bias,
                                               float* __restrict__ out,
                                               bool concat) {
    __shared__ float sOut[HC];
    int tid = threadIdx.x;
    int n = blockIdx.x;

    unsigned long long we2[RR][2];
    unsigned long long self0 = 0ull, self1 = 0ull;
    const unsigned long long half2 = pack2(SELF_FILL, SELF_FILL);
#pragma unroll
    for (int k = 0; k < RR; k++) {
        float4 w = *(const float4*)&We[k * HC + tid * 4];
        we2[k][0] = pack2(w.x, w.y);
        we2[k][1] = pack2(w.z, w.w);
        fma2(self0, half2, we2[k][0]);
        fma2(self1, half2, we2[k][1]);
    }

    float4 attv = ((const float4*)att)[tid];
    float4 xr4 = ((const float4*)(xr + (size_t)n * HC))[tid];

    float m = -1e30f, s = 0.f;
    float ax = 0.f, ay = 0.f, az = 0.f, aw = 0.f;
    int b = g_off[n], e = g_off[n + 1];
    for (int i = b; i < e; i++) {
        int src = g_csr_src[i];
        int eid = g_csr_eid[i];
        float4 xl4 = ((const float4*)(xl + (size_t)src * HC))[tid];
        float2 pa, pb;
        if (eid < NE) {
            const float4* er = (const float4*)(ea + (size_t)eid * RR);
            float4 e0 = er[0], e1 = er[1], e2 = er[2], e3 = er[3];
            float ev[RR] = {e0.x, e0.y, e0.z, e0.w, e1.x, e1.y, e1.z, e1.w,
                            e2.x, e2.y, e2.z, e2.w, e3.x, e3.y, e3.z, e3.w};
            unsigned long long p0 = 0ull, p1 = 0ull;
#pragma unroll
            for (int k = 0; k < RR; k++) {
                unsigned long long ee = pack2(ev[k], ev[k]);
                fma2(p0, ee, we2[k][0]);
                fma2(p1, ee, we2[k][1]);
            }
            pa = unpack2(p0); pb = unpack2(p1);
        } else {
            pa = unpack2(self0); pb = unpack2(self1);
        }
        float zx = xl4.x + xr4.x + pa.x; zx = zx > 0.f ? zx : NEG_SLOPE * zx;
        float zy = xl4.y + xr4.y + pa.y; zy = zy > 0.f ? zy : NEG_SLOPE * zy;
        float zz = xl4.z + xr4.z + pb.x; zz = zz > 0.f ? zz : NEG_SLOPE * zz;
        float zw = xl4.w + xr4.w + pb.y; zw = zw > 0.f ? zw : NEG_SLOPE * zw;
        float p = zx * attv.x + zy * attv.y + zz * attv.z + zw * attv.w;
        p += __shfl_xor_sync(~0u, p, 8);
        p += __shfl_xor_sync(~0u, p, 4);
        p += __shfl_xor_sync(~0u, p, 2);
        p += __shfl_xor_sync(~0u, p, 1);
        float mN = fmaxf(m, p);
        float sc = __expf(m - mN);
        float w  = __expf(p - mN);
        s  = s  * sc + w;
        ax = ax * sc + w * xl4.x;
        ay = ay * sc + w * xl4.y;
        az = az * sc + w * xl4.z;
        aw = aw * sc + w * xl4.w;
        m = mN;
    }
    float inv = 1.f / (s + 1e-16f);
    if (concat) {
        float4 o = make_float4(ax * inv + bias[tid * 4 + 0], ay * inv + bias[tid * 4 + 1],
                               az * inv + bias[tid * 4 + 2], aw * inv + bias[tid * 4 + 3]);
        size_t base = (size_t)n * HC + tid * 4;
        bf16 h0, l0, h1, l1, h2, l2, h3, l3;
        split1(o.x, h0, l0); split1(o.y, h1, l1);
        split1(o.z, h2, l2); split1(o.w, h3, l3);
        *(uint2*)&g_hs_hi[base] = make_uint2(pkbf(h0, h1), pkbf(h2, h3));
        *(uint2*)&g_hs_lo[base] = make_uint2(pkbf(l0, l1), pkbf(l2, l3));
    } else {
        sOut[tid * 4 + 0] = ax * inv; sOut[tid * 4 + 1] = ay * inv;
        sOut[tid * 4 + 2] = az * inv; sOut[tid * 4 + 3] = aw * inv;
        __syncthreads();
        if (tid < CC) {
            float acc = 0.f;
#pragma unroll
            for (int h = 0; h < HH; h++) acc += sOut[h * CC + tid];
            out[(size_t)n * CC + tid] = acc * (1.f / HH) + bias[tid];
        }
    }
}
__global__ __launch_bounds__(128) void k_edge1(const float* ea, const float* We,
                                               const float* att, const float* bias) {
    gat_edge_fused(g_xl1, g_xr1, ea, We, att, bias, nullptr, true);
}
__global__ __launch_bounds__(128) void k_edge2(const float* ea, const float* We,
                                               const float* att, const float* bias,
                                               float* out) {
    gat_edge_fused(g_xl2, g_xr2, ea, We, att, bias, out, false);
}

// ---------------- launch ----------------
extern "C" void kernel_launch(void* const* d_in, const int* in_sizes, int n_in,
                              void* d_out, int out_size) {
    const float* x     = (const float*)d_in[0];
    const void*  ei    = d_in[1];
    const float* ea    = (const float*)d_in[2];
    const float* Wl1   = (const float*)d_in[3];
    const float* bl1   = (const float*)d_in[4];
    const float* Wr1   = (const float*)d_in[5];
    const float* br1   = (const float*)d_in[6];
    const float* We1   = (const float*)d_in[7];
    const float* att1  = (const float*)d_in[8];
    const float* bias1 = (const float*)d_in[9];
    const float* Wl2   = (const float*)d_in[10];
    const float* bl2   = (const float*)d_in[11];
    const float* Wr2   = (const float*)d_in[12];
    const float* br2   = (const float*)d_in[13];
    const float* We2   = (const float*)d_in[14];
    const float* att2  = (const float*)d_in[15];
    const float* bias2 = (const float*)d_in[16];
    float* out = (float*)d_out;

    dim3 gm1(HC / 128, NN / 128, 3);     // GEMM pair + helper band
    dim3 gm2(HC / 128, NN / 128, 2);     // layer-2 GEMM pair

    k_prep1<<<8704, 256>>>(x, Wl1, Wr1);                        // 1
    k_mega1<<<gm1, 256>>>(bl1, br1, ei, Wl2, Wr2);              // 2
    k_scan<<<1, 1024>>>();                                      // 3
    k_scatter<<<(NEP + 255) / 256, 256>>>();                    // 4
    k_sort<<<(NN + 127) / 128, 128>>>();                        // 5  <- ncu slot lands near here
    k_edge1<<<NN, 128>>>(ea, We1, att1, bias1);                 // 6
    k_mma_x2<<<gm2, 256>>>(bl2, br2);                           // 7
    k_edge2<<<NN, 128>>>(ea, We2, att2, bias2, out);            // 8
}